// round 1
// baseline (speedup 1.0000x reference)
#include <cuda_runtime.h>

#define D 64
#define MAX_NODES 50000

// scratch for support = X @ W  (50000 x 64 f32 = 12.8 MB)
__device__ float g_support[MAX_NODES * D];

// ---------------------------------------------------------------------------
// support[n, c] = sum_k X[n, k] * W[k, c]
// One thread per output element. W (16 KB) staged in shared memory.
// ---------------------------------------------------------------------------
__global__ void gcn_gemm_kernel(const float* __restrict__ X,
                                const float* __restrict__ W,
                                int n_nodes) {
    __shared__ float sW[D * D];
    for (int i = threadIdx.x; i < D * D; i += blockDim.x) sW[i] = W[i];
    __syncthreads();

    int idx = blockIdx.x * blockDim.x + threadIdx.x;
    int total = n_nodes * D;
    if (idx >= total) return;

    int row = idx >> 6;
    int col = idx & 63;

    const float4* Xr = reinterpret_cast<const float4*>(X + row * D);
    float acc = 0.0f;
#pragma unroll
    for (int k4 = 0; k4 < D / 4; k4++) {
        float4 x = Xr[k4];  // broadcast across threads sharing this row
        acc += x.x * sW[(k4 * 4 + 0) * D + col];
        acc += x.y * sW[(k4 * 4 + 1) * D + col];
        acc += x.z * sW[(k4 * 4 + 2) * D + col];
        acc += x.w * sW[(k4 * 4 + 3) * D + col];
    }
    g_support[idx] = acc;
}

// ---------------------------------------------------------------------------
// out[n, c] = b[c]   (bias broadcast; d_out is poisoned before timing)
// ---------------------------------------------------------------------------
__global__ void gcn_init_kernel(float* __restrict__ out,
                                const float* __restrict__ b,
                                int total4) {
    int idx = blockIdx.x * blockDim.x + threadIdx.x;
    if (idx >= total4) return;
    const float4* b4 = reinterpret_cast<const float4*>(b);
    reinterpret_cast<float4*>(out)[idx] = b4[idx & (D / 4 - 1)];
}

// ---------------------------------------------------------------------------
// out[dst(e), :] += w_e * support[src(e), :]
// 16 lanes per edge; each lane handles one float4 (4 features) and issues a
// single vectorized L2 reduction (red.global.add.v4.f32 -> one REDG.128).
// ---------------------------------------------------------------------------
__global__ void gcn_scatter_kernel(const int* __restrict__ edge_src,
                                   const int* __restrict__ edge_dst,
                                   const float* __restrict__ edge_weight,
                                   float* __restrict__ out,
                                   int n_edges) {
    int t = blockIdx.x * blockDim.x + threadIdx.x;
    int e = t >> 4;
    if (e >= n_edges) return;
    int lane4 = (t & 15) << 2;  // feature offset 0..60 step 4

    int s = edge_src[e];
    int d = edge_dst[e];
    float we = edge_weight[e];

    float4 v = *reinterpret_cast<const float4*>(&g_support[s * D + lane4]);
    v.x *= we; v.y *= we; v.z *= we; v.w *= we;

    float* p = out + d * D + lane4;
    asm volatile("red.global.add.v4.f32 [%0], {%1, %2, %3, %4};"
                 :: "l"(p), "f"(v.x), "f"(v.y), "f"(v.z), "f"(v.w)
                 : "memory");
}

// ---------------------------------------------------------------------------
// Inputs (metadata order): X[f32 N*64], edge_src[i32 E], edge_dst[i32 E],
//                          edge_weight[f32 E], weight[f32 64*64], b[f32 64]
// Output: f32 [N, 64]
// ---------------------------------------------------------------------------
extern "C" void kernel_launch(void* const* d_in, const int* in_sizes, int n_in,
                              void* d_out, int out_size) {
    const float* X     = (const float*)d_in[0];
    const int*   esrc  = (const int*)d_in[1];
    const int*   edst  = (const int*)d_in[2];
    const float* ew    = (const float*)d_in[3];
    const float* W     = (const float*)d_in[4];
    const float* b     = (const float*)d_in[5];
    float*       out   = (float*)d_out;

    int n_nodes = in_sizes[0] / D;
    int n_edges = in_sizes[1];

    // 1) support = X @ W
    {
        int total = n_nodes * D;
        int threads = 256;
        int blocks = (total + threads - 1) / threads;
        gcn_gemm_kernel<<<blocks, threads>>>(X, W, n_nodes);
    }

    // 2) out = b (broadcast)
    {
        int total4 = n_nodes * D / 4;
        int threads = 256;
        int blocks = (total4 + threads - 1) / threads;
        gcn_init_kernel<<<blocks, threads>>>(out, b, total4);
    }

    // 3) scatter-add over edges
    {
        long long total = (long long)n_edges * 16;
        int threads = 256;
        int blocks = (int)((total + threads - 1) / threads);
        gcn_scatter_kernel<<<blocks, threads>>>(esrc, edst, ew, out, n_edges);
    }
}

// round 2
// speedup vs baseline: 1.1423x; 1.1423x over previous
#include <cuda_runtime.h>

#define D 64
#define MAX_NODES 50000
#define TILE_R 64   // rows per block

// scratch for support = X @ W  (50000 x 64 f32 = 12.8 MB)
__device__ float g_support[MAX_NODES * D];

// ---------------------------------------------------------------------------
// support = X @ W   — register-tiled: block = 64 rows x 64 cols,
// 256 threads, each thread a 4x4 register block.
// Xt staged TRANSPOSED in smem so the 4-row x vector is one LDS.128.
// ---------------------------------------------------------------------------
__global__ __launch_bounds__(256) void gcn_gemm_kernel(
    const float* __restrict__ X,
    const float* __restrict__ W,
    int n_nodes) {
    __shared__ float Xt[D][D];  // Xt[k][r]
    __shared__ float sW[D][D];  // sW[k][c]

    const int tid = threadIdx.x;
    const int row0 = blockIdx.x * TILE_R;

    // Load W (4096 floats) via float4: 1024 float4 / 256 threads = 4 each.
    {
        const float4* W4 = reinterpret_cast<const float4*>(W);
        float4* sW4 = reinterpret_cast<float4*>(&sW[0][0]);
#pragma unroll
        for (int j = 0; j < 4; j++) sW4[tid + j * 256] = W4[tid + j * 256];
    }

    // Load X tile transposed. Thread t covers row r = t>>2, k4 chunks (t&3)+4j.
    {
        const int r = tid >> 2;
        const int grow = row0 + r;
#pragma unroll
        for (int j = 0; j < 4; j++) {
            const int k = ((tid & 3) + j * 4) * 4;
            float4 v;
            if (grow < n_nodes)
                v = *reinterpret_cast<const float4*>(X + grow * D + k);
            else
                v = make_float4(0.f, 0.f, 0.f, 0.f);
            Xt[k + 0][r] = v.x;
            Xt[k + 1][r] = v.y;
            Xt[k + 2][r] = v.z;
            Xt[k + 3][r] = v.w;
        }
    }
    __syncthreads();

    const int tc = (tid & 15) * 4;  // col group
    const int tr = (tid >> 4) * 4;  // row group

    float acc[4][4] = {};
#pragma unroll 8
    for (int k = 0; k < D; k++) {
        const float4 x = *reinterpret_cast<const float4*>(&Xt[k][tr]);
        const float4 w = *reinterpret_cast<const float4*>(&sW[k][tc]);
        acc[0][0] += x.x * w.x; acc[0][1] += x.x * w.y; acc[0][2] += x.x * w.z; acc[0][3] += x.x * w.w;
        acc[1][0] += x.y * w.x; acc[1][1] += x.y * w.y; acc[1][2] += x.y * w.z; acc[1][3] += x.y * w.w;
        acc[2][0] += x.z * w.x; acc[2][1] += x.z * w.y; acc[2][2] += x.z * w.z; acc[2][3] += x.z * w.w;
        acc[3][0] += x.w * w.x; acc[3][1] += x.w * w.y; acc[3][2] += x.w * w.z; acc[3][3] += x.w * w.w;
    }

#pragma unroll
    for (int i = 0; i < 4; i++) {
        const int grow = row0 + tr + i;
        if (grow < n_nodes) {
            float4 v = make_float4(acc[i][0], acc[i][1], acc[i][2], acc[i][3]);
            *reinterpret_cast<float4*>(&g_support[grow * D + tc]) = v;
        }
    }
}

// ---------------------------------------------------------------------------
// out[n, c] = b[c]   (bias broadcast; d_out is poisoned before timing)
// ---------------------------------------------------------------------------
__global__ void gcn_init_kernel(float* __restrict__ out,
                                const float* __restrict__ b,
                                int total4) {
    int idx = blockIdx.x * blockDim.x + threadIdx.x;
    if (idx >= total4) return;
    const float4* b4 = reinterpret_cast<const float4*>(b);
    reinterpret_cast<float4*>(out)[idx] = b4[idx & (D / 4 - 1)];
}

// ---------------------------------------------------------------------------
// out[dst(e), :] += w_e * support[src(e), :]
// 16 lanes per edge; each lane one float4 gather + one red.global.add.v4.f32.
// ---------------------------------------------------------------------------
__global__ void gcn_scatter_kernel(const int* __restrict__ edge_src,
                                   const int* __restrict__ edge_dst,
                                   const float* __restrict__ edge_weight,
                                   float* __restrict__ out,
                                   int n_edges) {
    int t = blockIdx.x * blockDim.x + threadIdx.x;
    int e = t >> 4;
    if (e >= n_edges) return;
    int lane4 = (t & 15) << 2;

    int s = edge_src[e];
    int d = edge_dst[e];
    float we = edge_weight[e];

    float4 v = *reinterpret_cast<const float4*>(&g_support[s * D + lane4]);
    v.x *= we; v.y *= we; v.z *= we; v.w *= we;

    float* p = out + d * D + lane4;
    asm volatile("red.global.add.v4.f32 [%0], {%1, %2, %3, %4};"
                 :: "l"(p), "f"(v.x), "f"(v.y), "f"(v.z), "f"(v.w)
                 : "memory");
}

// ---------------------------------------------------------------------------
extern "C" void kernel_launch(void* const* d_in, const int* in_sizes, int n_in,
                              void* d_out, int out_size) {
    const float* X    = (const float*)d_in[0];
    const int*   esrc = (const int*)d_in[1];
    const int*   edst = (const int*)d_in[2];
    const float* ew   = (const float*)d_in[3];
    const float* W    = (const float*)d_in[4];
    const float* b    = (const float*)d_in[5];
    float*       out  = (float*)d_out;

    int n_nodes = in_sizes[0] / D;
    int n_edges = in_sizes[1];

    // 1) support = X @ W  (register-tiled)
    {
        int blocks = (n_nodes + TILE_R - 1) / TILE_R;
        gcn_gemm_kernel<<<blocks, 256>>>(X, W, n_nodes);
    }

    // 2) out = b (broadcast)
    {
        int total4 = n_nodes * D / 4;
        gcn_init_kernel<<<(total4 + 255) / 256, 256>>>(out, b, total4);
    }

    // 3) scatter-add over edges
    {
        long long total = (long long)n_edges * 16;
        int blocks = (int)((total + 255) / 256);
        gcn_scatter_kernel<<<blocks, 256>>>(esrc, edst, ew, out, n_edges);
    }
}

// round 3
// speedup vs baseline: 1.5725x; 1.3766x over previous
#include <cuda_runtime.h>

#define D 64
#define MAX_NODES 50000
#define MAX_EDGES 800000
#define SCAN_BLK 1024
#define NB_SCAN ((MAX_NODES + SCAN_BLK - 1) / SCAN_BLK)   // 49

// ---- scratch ----
__device__ float g_support[MAX_NODES * D];   // X @ W
__device__ int   g_deg[MAX_NODES];
__device__ int   g_offsets[MAX_NODES];       // exclusive prefix of deg
__device__ int   g_cursor[MAX_NODES];        // fill cursors; == row end after fill
__device__ int   g_blocksum[NB_SCAN];
__device__ int   g_blockoff[NB_SCAN];
__device__ int2  g_edges[MAX_EDGES];         // (src, bitcast(w)) bucketed by dst

// ---------------------------------------------------------------------------
// support = X @ W : 64-row tiles, 256 threads, 4x4 register blocking.
// ---------------------------------------------------------------------------
__global__ __launch_bounds__(256) void gcn_gemm_kernel(
    const float* __restrict__ X, const float* __restrict__ W, int n_nodes) {
    __shared__ float Xt[D][D];  // Xt[k][r]
    __shared__ float sW[D][D];  // sW[k][c]

    const int tid = threadIdx.x;
    const int row0 = blockIdx.x * D;

    {
        const float4* W4 = reinterpret_cast<const float4*>(W);
        float4* sW4 = reinterpret_cast<float4*>(&sW[0][0]);
#pragma unroll
        for (int j = 0; j < 4; j++) sW4[tid + j * 256] = W4[tid + j * 256];
    }
    {
        const int r = tid >> 2;
        const int grow = row0 + r;
#pragma unroll
        for (int j = 0; j < 4; j++) {
            const int k = ((tid & 3) + j * 4) * 4;
            float4 v = make_float4(0.f, 0.f, 0.f, 0.f);
            if (grow < n_nodes)
                v = *reinterpret_cast<const float4*>(X + grow * D + k);
            Xt[k + 0][r] = v.x; Xt[k + 1][r] = v.y;
            Xt[k + 2][r] = v.z; Xt[k + 3][r] = v.w;
        }
    }
    __syncthreads();

    const int tc = (tid & 15) * 4;
    const int tr = (tid >> 4) * 4;

    float acc[4][4] = {};
#pragma unroll 8
    for (int k = 0; k < D; k++) {
        const float4 x = *reinterpret_cast<const float4*>(&Xt[k][tr]);
        const float4 w = *reinterpret_cast<const float4*>(&sW[k][tc]);
        acc[0][0] += x.x * w.x; acc[0][1] += x.x * w.y; acc[0][2] += x.x * w.z; acc[0][3] += x.x * w.w;
        acc[1][0] += x.y * w.x; acc[1][1] += x.y * w.y; acc[1][2] += x.y * w.z; acc[1][3] += x.y * w.w;
        acc[2][0] += x.z * w.x; acc[2][1] += x.z * w.y; acc[2][2] += x.z * w.z; acc[2][3] += x.z * w.w;
        acc[3][0] += x.w * w.x; acc[3][1] += x.w * w.y; acc[3][2] += x.w * w.z; acc[3][3] += x.w * w.w;
    }
#pragma unroll
    for (int i = 0; i < 4; i++) {
        const int grow = row0 + tr + i;
        if (grow < n_nodes)
            *reinterpret_cast<float4*>(&g_support[grow * D + tc]) =
                make_float4(acc[i][0], acc[i][1], acc[i][2], acc[i][3]);
    }
}

// ---------------------------------------------------------------------------
__global__ void zero_deg_kernel(int n) {
    int i = blockIdx.x * blockDim.x + threadIdx.x;
    if (i < n) g_deg[i] = 0;
}

__global__ void count_kernel(const int* __restrict__ edge_dst, int n_edges) {
    int e = blockIdx.x * blockDim.x + threadIdx.x;
    if (e < n_edges) atomicAdd(&g_deg[edge_dst[e]], 1);  // no return -> RED
}

// per-1024-chunk sums
__global__ __launch_bounds__(SCAN_BLK) void scan_sums_kernel(int n) {
    int i = blockIdx.x * SCAN_BLK + threadIdx.x;
    int v = (i < n) ? g_deg[i] : 0;
#pragma unroll
    for (int o = 16; o; o >>= 1) v += __shfl_down_sync(0xffffffffu, v, o);
    __shared__ int ws[32];
    if ((threadIdx.x & 31) == 0) ws[threadIdx.x >> 5] = v;
    __syncthreads();
    if (threadIdx.x < 32) {
        int s = ws[threadIdx.x];
#pragma unroll
        for (int o = 16; o; o >>= 1) s += __shfl_down_sync(0xffffffffu, s, o);
        if (threadIdx.x == 0) g_blocksum[blockIdx.x] = s;
    }
}

// sequential exclusive scan over NB_SCAN partials (tiny)
__global__ void scan_partials_kernel(int nb) {
    if (threadIdx.x == 0 && blockIdx.x == 0) {
        int run = 0;
        for (int i = 0; i < nb; i++) { g_blockoff[i] = run; run += g_blocksum[i]; }
    }
}

// final: exclusive scan within chunk + chunk offset -> offsets, cursor
__global__ __launch_bounds__(SCAN_BLK) void scan_final_kernel(int n) {
    int i = blockIdx.x * SCAN_BLK + threadIdx.x;
    int v = (i < n) ? g_deg[i] : 0;
    int lane = threadIdx.x & 31, wp = threadIdx.x >> 5;
    int x = v;
#pragma unroll
    for (int o = 1; o < 32; o <<= 1) {
        int t = __shfl_up_sync(0xffffffffu, x, o);
        if (lane >= o) x += t;
    }
    __shared__ int ws[32];
    if (lane == 31) ws[wp] = x;
    __syncthreads();
    if (wp == 0) {
        int s = ws[lane];
#pragma unroll
        for (int o = 1; o < 32; o <<= 1) {
            int t = __shfl_up_sync(0xffffffffu, s, o);
            if (lane >= o) s += t;
        }
        ws[lane] = s;
    }
    __syncthreads();
    int excl = x - v + (wp > 0 ? ws[wp - 1] : 0) + g_blockoff[blockIdx.x];
    if (i < n) { g_offsets[i] = excl; g_cursor[i] = excl; }
}

// bucket edges by dst
__global__ void fill_kernel(const int* __restrict__ edge_src,
                            const int* __restrict__ edge_dst,
                            const float* __restrict__ edge_weight, int n_edges) {
    int e = blockIdx.x * blockDim.x + threadIdx.x;
    if (e >= n_edges) return;
    int slot = atomicAdd(&g_cursor[edge_dst[e]], 1);
    g_edges[slot] = make_int2(edge_src[e], __float_as_int(edge_weight[e]));
}

// ---------------------------------------------------------------------------
// gather: one warp per node; lane l owns features [2l, 2l+1] (float2).
// out[n] = b + sum_e w_e * support[src_e]
// ---------------------------------------------------------------------------
__global__ __launch_bounds__(256) void gather_kernel(
    const float* __restrict__ b, float* __restrict__ out, int n_nodes) {
    int warp = (blockIdx.x * blockDim.x + threadIdx.x) >> 5;
    int lane = threadIdx.x & 31;
    if (warp >= n_nodes) return;

    int start = g_offsets[warp];
    int end = g_cursor[warp];  // cursor == row end after fill

    float2 acc = make_float2(0.f, 0.f);
    for (int p = start; p < end; p += 32) {
        int m = end - p; if (m > 32) m = 32;
        int2 ed = make_int2(0, 0);
        if (lane < m) ed = g_edges[p + lane];
        for (int j = 0; j < m; j++) {
            int s = __shfl_sync(0xffffffffu, ed.x, j);
            float wv = __int_as_float(__shfl_sync(0xffffffffu, ed.y, j));
            float2 v = reinterpret_cast<const float2*>(&g_support[s * D])[lane];
            acc.x += wv * v.x;
            acc.y += wv * v.y;
        }
    }
    float2 bb = reinterpret_cast<const float2*>(b)[lane];
    acc.x += bb.x; acc.y += bb.y;
    reinterpret_cast<float2*>(out + warp * D)[lane] = acc;
}

// ---------------------------------------------------------------------------
extern "C" void kernel_launch(void* const* d_in, const int* in_sizes, int n_in,
                              void* d_out, int out_size) {
    const float* X    = (const float*)d_in[0];
    const int*   esrc = (const int*)d_in[1];
    const int*   edst = (const int*)d_in[2];
    const float* ew   = (const float*)d_in[3];
    const float* W    = (const float*)d_in[4];
    const float* b    = (const float*)d_in[5];
    float*       out  = (float*)d_out;

    int n_nodes = in_sizes[0] / D;
    int n_edges = in_sizes[1];
    int nb_scan = (n_nodes + SCAN_BLK - 1) / SCAN_BLK;

    gcn_gemm_kernel<<<(n_nodes + D - 1) / D, 256>>>(X, W, n_nodes);

    zero_deg_kernel<<<(n_nodes + 255) / 256, 256>>>(n_nodes);
    count_kernel<<<(n_edges + 255) / 256, 256>>>(edst, n_edges);
    scan_sums_kernel<<<nb_scan, SCAN_BLK>>>(n_nodes);
    scan_partials_kernel<<<1, 32>>>(nb_scan);
    scan_final_kernel<<<nb_scan, SCAN_BLK>>>(n_nodes);
    fill_kernel<<<(n_edges + 255) / 256, 256>>>(esrc, edst, ew, n_edges);

    int warps = n_nodes;  // one warp per node
    gather_kernel<<<(warps * 32 + 255) / 256, 256>>>(b, out, n_nodes);
}